// round 13
// baseline (speedup 1.0000x reference)
#include <cuda_runtime.h>
#include <stdint.h>

// ---------------------------------------------------------------------------
// Raindrop ObservationPropagation, use_beta=False, heads=1.
// Identity: segment softmax sums to exactly 1 and the message uses x[tgt]
// (constant within each segment), so
//   out[n] = relu(x[n] @ Wv + bv) * has_incoming_edge[n]
// edge_weights cancel. Work = edge-target mask scatter + masked 50000x96x96
// GEMM (bias+relu epilogue).
//
// R13: tcgen05 is unavailable (harness compiles PTX for sm_103, not sm_103a).
// R8 GEMM was latency-bound at 12 warps/SM (occ 16%, issue 47%, nothing
// saturated) -- limiter was 63KB smem/CTA. Drop the 36KB W staging: W is
// small (36KB), fully L1-resident, and every read is warp-coalesced, so
// __ldg serves it at ~L1-hit latency. smem 63->26.6KB => 5 CTAs/SM
// (reg-bound at 102 regs) = 20 warps/SM, and the whole W prologue vanishes.
// ---------------------------------------------------------------------------

#define DIM 96
#define RPB 64            // rows per block (4 warps x 16 rows)
#define SXT_S 68          // tile stride: lane k-stride = 68 words = 4 banks -> 0 conflicts
#define MAX_NODES (1 << 16)

__device__ unsigned char g_mask[MAX_NODES];   // zero-initialized at module load

// mask[tgt[e]] = 1; 4 edges/thread. Per-block width detection: warp 0 probes
// the first 32 64-bit words (source row; in-bounds under both widths):
// int64 -> values in [0,n); int32 -> packed pair >= 2^32 almost surely.
__global__ void rd_scatter_kernel(const void* __restrict__ ei,
                                  long long E, int n_nodes) {
    __shared__ int s_is64;
    const int tid = threadIdx.x;
    if (tid < 32) {
        long long v = ((const long long*)ei)[tid];
        bool bad = (v < 0 || v >= (long long)n_nodes);
        unsigned b = __ballot_sync(0xffffffffu, bad);
        if (tid == 0) s_is64 = (b == 0);
    }
    __syncthreads();
    const bool is64 = s_is64;

    long long q = (long long)blockIdx.x * blockDim.x + tid;  // quad index
    long long e = q * 4;
    if (e >= E) return;
    long long t[4];
    int cnt;
    if (e + 4 <= E) {
        cnt = 4;
        if (is64) {
            const longlong2* tp = (const longlong2*)((const long long*)ei + E);
            longlong2 v0 = tp[q * 2];
            longlong2 v1 = tp[q * 2 + 1];
            t[0] = v0.x; t[1] = v0.y; t[2] = v1.x; t[3] = v1.y;
        } else {
            const int4* tp = (const int4*)((const int*)ei + E);
            int4 v = tp[q];
            t[0] = v.x; t[1] = v.y; t[2] = v.z; t[3] = v.w;
        }
    } else {
        cnt = (int)(E - e);
        for (int i = 0; i < cnt; i++) {
            if (is64) t[i] = ((const long long*)ei)[E + e + i];
            else      t[i] = (long long)((const int*)ei)[E + e + i];
        }
    }
#pragma unroll
    for (int i = 0; i < 4; i++) {
        if (i < cnt && t[i] >= 0 && t[i] < (long long)n_nodes)
            g_mask[t[i]] = 1;           // idempotent unconditional byte store
    }
}

// out[n] = mask[n] * relu(x[n] @ Wv + bv)
// Block 128 = 4 warps, 64 rows. Warp w owns rows [16w, 16w+16); lane tx owns
// cols {tx, tx+32, tx+64}. x tile k-major sXT[k][row], stride 68 (STS
// transpose + broadcast LDS.128 conflict-free). Weights read straight from
// global via __ldg: per warp-k the 3 reads are consecutive-lane-coalesced
// 128B runs of a 36KB L1-resident table.
__global__ __launch_bounds__(128, 5)
void rd_gemm_kernel(const float* __restrict__ x,
                    const float* __restrict__ Wv,
                    const float* __restrict__ bv,
                    float* __restrict__ out, int n) {
    __shared__ float sB[DIM];
    __shared__ __align__(16) float sXT[DIM][SXT_S];     // 26112 B

    const int tid  = threadIdx.x;
    const int row0 = blockIdx.x * RPB;

    if (tid < DIM) sB[tid] = bv[tid];

    // Conflict-free transposed tile load: unit u = rg*96 + k (rg = row-group
    // of 4). Thread gathers rows rg*4..rg*4+3 at column k (coalesced across
    // consecutive-k lanes), stores ONE STS.128 at sXT[k][rg*4] (lane k-stride
    // 68 words = 4 banks; conflict-free phases).
    const bool full = (row0 + RPB <= n);
#pragma unroll
    for (int it = 0; it < 12; it++) {
        int u  = tid + 128 * it;        // 0..1535
        int rg = u / DIM;               // 0..15
        int k  = u - rg * DIM;          // 0..95
        int r  = row0 + rg * 4;
        float v0 = 0.f, v1 = 0.f, v2 = 0.f, v3 = 0.f;
        if (full) {
            v0 = x[(size_t)(r + 0) * DIM + k];
            v1 = x[(size_t)(r + 1) * DIM + k];
            v2 = x[(size_t)(r + 2) * DIM + k];
            v3 = x[(size_t)(r + 3) * DIM + k];
        } else {
            if (r + 0 < n) v0 = x[(size_t)(r + 0) * DIM + k];
            if (r + 1 < n) v1 = x[(size_t)(r + 1) * DIM + k];
            if (r + 2 < n) v2 = x[(size_t)(r + 2) * DIM + k];
            if (r + 3 < n) v3 = x[(size_t)(r + 3) * DIM + k];
        }
        *(float4*)&sXT[k][rg * 4] = make_float4(v0, v1, v2, v3);
    }
    __syncthreads();

    const int tx = tid & 31;
    const int wr = (tid >> 5) * 16;     // first of this warp's 16 rows
    const float* Wl = Wv + tx;          // lane-local W column base

    float a0[16], a1[16], a2[16];       // [row][col-group]
#pragma unroll
    for (int r = 0; r < 16; r++) { a0[r] = 0.f; a1[r] = 0.f; a2[r] = 0.f; }

    // unroll 2: 48 accumulators + pipelined LDS/LDG results stay under the
    // 102-reg cap -> no local-memory spills (the R3/R4 killer).
#pragma unroll 2
    for (int k = 0; k < DIM; k++) {
        float4 xa = *(const float4*)&sXT[k][wr];        // rows 0..3 (broadcast)
        float4 xb = *(const float4*)&sXT[k][wr + 4];    // rows 4..7
        float4 xc = *(const float4*)&sXT[k][wr + 8];    // rows 8..11
        float4 xd = *(const float4*)&sXT[k][wr + 12];   // rows 12..15
        float w0 = __ldg(Wl + k * DIM);
        float w1 = __ldg(Wl + k * DIM + 32);
        float w2 = __ldg(Wl + k * DIM + 64);
        a0[ 0] = fmaf(xa.x, w0, a0[ 0]); a1[ 0] = fmaf(xa.x, w1, a1[ 0]); a2[ 0] = fmaf(xa.x, w2, a2[ 0]);
        a0[ 1] = fmaf(xa.y, w0, a0[ 1]); a1[ 1] = fmaf(xa.y, w1, a1[ 1]); a2[ 1] = fmaf(xa.y, w2, a2[ 1]);
        a0[ 2] = fmaf(xa.z, w0, a0[ 2]); a1[ 2] = fmaf(xa.z, w1, a1[ 2]); a2[ 2] = fmaf(xa.z, w2, a2[ 2]);
        a0[ 3] = fmaf(xa.w, w0, a0[ 3]); a1[ 3] = fmaf(xa.w, w1, a1[ 3]); a2[ 3] = fmaf(xa.w, w2, a2[ 3]);
        a0[ 4] = fmaf(xb.x, w0, a0[ 4]); a1[ 4] = fmaf(xb.x, w1, a1[ 4]); a2[ 4] = fmaf(xb.x, w2, a2[ 4]);
        a0[ 5] = fmaf(xb.y, w0, a0[ 5]); a1[ 5] = fmaf(xb.y, w1, a1[ 5]); a2[ 5] = fmaf(xb.y, w2, a2[ 5]);
        a0[ 6] = fmaf(xb.z, w0, a0[ 6]); a1[ 6] = fmaf(xb.z, w1, a1[ 6]); a2[ 6] = fmaf(xb.z, w2, a2[ 6]);
        a0[ 7] = fmaf(xb.w, w0, a0[ 7]); a1[ 7] = fmaf(xb.w, w1, a1[ 7]); a2[ 7] = fmaf(xb.w, w2, a2[ 7]);
        a0[ 8] = fmaf(xc.x, w0, a0[ 8]); a1[ 8] = fmaf(xc.x, w1, a1[ 8]); a2[ 8] = fmaf(xc.x, w2, a2[ 8]);
        a0[ 9] = fmaf(xc.y, w0, a0[ 9]); a1[ 9] = fmaf(xc.y, w1, a1[ 9]); a2[ 9] = fmaf(xc.y, w2, a2[ 9]);
        a0[10] = fmaf(xc.z, w0, a0[10]); a1[10] = fmaf(xc.z, w1, a1[10]); a2[10] = fmaf(xc.z, w2, a2[10]);
        a0[11] = fmaf(xc.w, w0, a0[11]); a1[11] = fmaf(xc.w, w1, a1[11]); a2[11] = fmaf(xc.w, w2, a2[11]);
        a0[12] = fmaf(xd.x, w0, a0[12]); a1[12] = fmaf(xd.x, w1, a1[12]); a2[12] = fmaf(xd.x, w2, a2[12]);
        a0[13] = fmaf(xd.y, w0, a0[13]); a1[13] = fmaf(xd.y, w1, a1[13]); a2[13] = fmaf(xd.y, w2, a2[13]);
        a0[14] = fmaf(xd.z, w0, a0[14]); a1[14] = fmaf(xd.z, w1, a1[14]); a2[14] = fmaf(xd.z, w2, a2[14]);
        a0[15] = fmaf(xd.w, w0, a0[15]); a1[15] = fmaf(xd.w, w1, a1[15]); a2[15] = fmaf(xd.w, w2, a2[15]);
    }

    const float b0 = sB[tx];
    const float b1 = sB[tx + 32];
    const float b2 = sB[tx + 64];

#pragma unroll
    for (int i = 0; i < 16; i++) {
        int r = row0 + wr + i;
        if (r < n) {
            float m = g_mask[r] ? 1.f : 0.f;
            float* o = out + (size_t)r * DIM;
            o[tx]      = fmaxf(a0[i] + b0, 0.f) * m;
            o[tx + 32] = fmaxf(a1[i] + b1, 0.f) * m;
            o[tx + 64] = fmaxf(a2[i] + b2, 0.f) * m;
        }
    }
}

extern "C" void kernel_launch(void* const* d_in, const int* in_sizes, int n_in,
                              void* d_out, int out_size) {
    const float* x  = (const float*)d_in[0];
    // d_in[1] = p_t (unused, use_beta=False)
    const float* Wv = (const float*)d_in[2];
    const float* bv = (const float*)d_in[3];
    // d_in[4] = edge_weights (cancels: segment softmax sums to 1)
    const void*  ei = d_in[5];

    const int n = in_sizes[0] / DIM;                 // 50000
    const long long E = (long long)in_sizes[5] / 2;  // 800000

    {   // 1) fused detect + scatter (4 edges/thread)
        long long quads = (E + 3) / 4;
        int threads = 256;
        int blocks = (int)((quads + threads - 1) / threads);
        rd_scatter_kernel<<<blocks, threads>>>(ei, E, n);
    }
    {   // 2) masked GEMM + bias + relu
        int blocks = (n + RPB - 1) / RPB;
        rd_gemm_kernel<<<blocks, 128>>>(x, Wv, bv, (float*)d_out, n);
    }
}

// round 16
// speedup vs baseline: 1.2012x; 1.2012x over previous
#include <cuda_runtime.h>
#include <stdint.h>

// ---------------------------------------------------------------------------
// Raindrop ObservationPropagation, use_beta=False, heads=1.
// Identity: segment softmax sums to exactly 1 and the message uses x[tgt]
// (constant within each segment), so
//   out[n] = relu(x[n] @ Wv + bv) * has_incoming_edge[n]
// edge_weights cancel. Work = edge-target mask scatter + masked 50000x96x96
// GEMM (bias+relu epilogue).
//
// R14: revert R13's inner-loop __ldg (long-scoreboard latency regressed 40%).
// Keep R8's proven smem-W inner loop; raise occupancy + cut wave tail by
// doubling the CTA: 256 threads, RPB=128 (same 16 rows/warp shape).
// smem 88KB -> 2 CTAs/SM = 16 warps/SM (R8: 12); grid 391 -> 1.32 waves
// (R8: 1.76); W-staging traffic halves.
// ---------------------------------------------------------------------------

#define DIM 96
#define RPB 128           // rows per block (8 warps x 16 rows)
#define SXT_S 132         // tile stride: lane k-stride = 132 % 32 = 4 banks -> 0 conflicts
#define MAX_NODES (1 << 16)

__device__ unsigned char g_mask[MAX_NODES];   // zero-initialized at module load

// mask[tgt[e]] = 1; 4 edges/thread. Per-block width detection: warp 0 probes
// the first 32 64-bit words (source row; in-bounds under both widths):
// int64 -> values in [0,n); int32 -> packed pair >= 2^32 almost surely.
__global__ void rd_scatter_kernel(const void* __restrict__ ei,
                                  long long E, int n_nodes) {
    __shared__ int s_is64;
    const int tid = threadIdx.x;
    if (tid < 32) {
        long long v = ((const long long*)ei)[tid];
        bool bad = (v < 0 || v >= (long long)n_nodes);
        unsigned b = __ballot_sync(0xffffffffu, bad);
        if (tid == 0) s_is64 = (b == 0);
    }
    __syncthreads();
    const bool is64 = s_is64;

    long long q = (long long)blockIdx.x * blockDim.x + tid;  // quad index
    long long e = q * 4;
    if (e >= E) return;
    long long t[4];
    int cnt;
    if (e + 4 <= E) {
        cnt = 4;
        if (is64) {
            const longlong2* tp = (const longlong2*)((const long long*)ei + E);
            longlong2 v0 = tp[q * 2];
            longlong2 v1 = tp[q * 2 + 1];
            t[0] = v0.x; t[1] = v0.y; t[2] = v1.x; t[3] = v1.y;
        } else {
            const int4* tp = (const int4*)((const int*)ei + E);
            int4 v = tp[q];
            t[0] = v.x; t[1] = v.y; t[2] = v.z; t[3] = v.w;
        }
    } else {
        cnt = (int)(E - e);
        for (int i = 0; i < cnt; i++) {
            if (is64) t[i] = ((const long long*)ei)[E + e + i];
            else      t[i] = (long long)((const int*)ei)[E + e + i];
        }
    }
#pragma unroll
    for (int i = 0; i < 4; i++) {
        if (i < cnt && t[i] >= 0 && t[i] < (long long)n_nodes)
            g_mask[t[i]] = 1;           // idempotent unconditional byte store
    }
}

// out[n] = mask[n] * relu(x[n] @ Wv + bv)
// Block 256 = 8 warps, 128 rows. Warp w owns rows [16w, 16w+16); lane tx owns
// cols {tx, tx+32, tx+64}. x tile k-major sXT[k][row], stride 132 words (both
// STS transpose and broadcast LDS.128 conflict-free: bank = 4*(k+rg) mod 32).
// Per warp-k: 4 broadcast LDS.128 + 3 warp LDS.32 + 48 FFMA.
__global__ __launch_bounds__(256, 2)
void rd_gemm_kernel(const float* __restrict__ x,
                    const float* __restrict__ Wv,
                    const float* __restrict__ bv,
                    float* __restrict__ out, int n) {
    __shared__ float sW[DIM * DIM];                     // 36864 B
    __shared__ float sB[DIM];
    __shared__ __align__(16) float sXT[DIM][SXT_S];     // 50688 B

    const int tid  = threadIdx.x;
    const int row0 = blockIdx.x * RPB;

    // Wv: 2304 float4, 9 per thread.
    {
        const float4* W4 = (const float4*)Wv;
        float4* sW4 = (float4*)sW;
#pragma unroll
        for (int i = 0; i < 9; i++) sW4[tid + 256 * i] = W4[tid + 256 * i];
    }
    if (tid < DIM) sB[tid] = bv[tid];

    // Conflict-free transposed tile load: unit u = rg*96 + k (rg = row-group
    // of 4, rg 0..31). Thread gathers rows rg*4..rg*4+3 at column k
    // (coalesced across consecutive-k lanes), stores ONE STS.128 at
    // sXT[k][rg*4].
    const bool full = (row0 + RPB <= n);
#pragma unroll
    for (int it = 0; it < 12; it++) {
        int u  = tid + 256 * it;        // 0..3071
        int rg = u / DIM;               // 0..31
        int k  = u - rg * DIM;          // 0..95
        int r  = row0 + rg * 4;
        float v0 = 0.f, v1 = 0.f, v2 = 0.f, v3 = 0.f;
        if (full) {
            v0 = x[(size_t)(r + 0) * DIM + k];
            v1 = x[(size_t)(r + 1) * DIM + k];
            v2 = x[(size_t)(r + 2) * DIM + k];
            v3 = x[(size_t)(r + 3) * DIM + k];
        } else {
            if (r + 0 < n) v0 = x[(size_t)(r + 0) * DIM + k];
            if (r + 1 < n) v1 = x[(size_t)(r + 1) * DIM + k];
            if (r + 2 < n) v2 = x[(size_t)(r + 2) * DIM + k];
            if (r + 3 < n) v3 = x[(size_t)(r + 3) * DIM + k];
        }
        *(float4*)&sXT[k][rg * 4] = make_float4(v0, v1, v2, v3);
    }
    __syncthreads();

    const int tx = tid & 31;
    const int wr = (tid >> 5) * 16;     // first of this warp's 16 rows

    float a0[16], a1[16], a2[16];       // [row][col-group]
#pragma unroll
    for (int r = 0; r < 16; r++) { a0[r] = 0.f; a1[r] = 0.f; a2[r] = 0.f; }

    // unroll 2: 48 accumulators + pipelined live values stay under the
    // 128-reg cap -> no local-memory spills (the R3/R4 killer).
#pragma unroll 2
    for (int k = 0; k < DIM; k++) {
        float4 xa = *(const float4*)&sXT[k][wr];        // rows 0..3 (broadcast)
        float4 xb = *(const float4*)&sXT[k][wr + 4];    // rows 4..7
        float4 xc = *(const float4*)&sXT[k][wr + 8];    // rows 8..11
        float4 xd = *(const float4*)&sXT[k][wr + 12];   // rows 12..15
        float w0 = sW[k * DIM + tx];
        float w1 = sW[k * DIM + tx + 32];
        float w2 = sW[k * DIM + tx + 64];
        a0[ 0] = fmaf(xa.x, w0, a0[ 0]); a1[ 0] = fmaf(xa.x, w1, a1[ 0]); a2[ 0] = fmaf(xa.x, w2, a2[ 0]);
        a0[ 1] = fmaf(xa.y, w0, a0[ 1]); a1[ 1] = fmaf(xa.y, w1, a1[ 1]); a2[ 1] = fmaf(xa.y, w2, a2[ 1]);
        a0[ 2] = fmaf(xa.z, w0, a0[ 2]); a1[ 2] = fmaf(xa.z, w1, a1[ 2]); a2[ 2] = fmaf(xa.z, w2, a2[ 2]);
        a0[ 3] = fmaf(xa.w, w0, a0[ 3]); a1[ 3] = fmaf(xa.w, w1, a1[ 3]); a2[ 3] = fmaf(xa.w, w2, a2[ 3]);
        a0[ 4] = fmaf(xb.x, w0, a0[ 4]); a1[ 4] = fmaf(xb.x, w1, a1[ 4]); a2[ 4] = fmaf(xb.x, w2, a2[ 4]);
        a0[ 5] = fmaf(xb.y, w0, a0[ 5]); a1[ 5] = fmaf(xb.y, w1, a1[ 5]); a2[ 5] = fmaf(xb.y, w2, a2[ 5]);
        a0[ 6] = fmaf(xb.z, w0, a0[ 6]); a1[ 6] = fmaf(xb.z, w1, a1[ 6]); a2[ 6] = fmaf(xb.z, w2, a2[ 6]);
        a0[ 7] = fmaf(xb.w, w0, a0[ 7]); a1[ 7] = fmaf(xb.w, w1, a1[ 7]); a2[ 7] = fmaf(xb.w, w2, a2[ 7]);
        a0[ 8] = fmaf(xc.x, w0, a0[ 8]); a1[ 8] = fmaf(xc.x, w1, a1[ 8]); a2[ 8] = fmaf(xc.x, w2, a2[ 8]);
        a0[ 9] = fmaf(xc.y, w0, a0[ 9]); a1[ 9] = fmaf(xc.y, w1, a1[ 9]); a2[ 9] = fmaf(xc.y, w2, a2[ 9]);
        a0[10] = fmaf(xc.z, w0, a0[10]); a1[10] = fmaf(xc.z, w1, a1[10]); a2[10] = fmaf(xc.z, w2, a2[10]);
        a0[11] = fmaf(xc.w, w0, a0[11]); a1[11] = fmaf(xc.w, w1, a1[11]); a2[11] = fmaf(xc.w, w2, a2[11]);
        a0[12] = fmaf(xd.x, w0, a0[12]); a1[12] = fmaf(xd.x, w1, a1[12]); a2[12] = fmaf(xd.x, w2, a2[12]);
        a0[13] = fmaf(xd.y, w0, a0[13]); a1[13] = fmaf(xd.y, w1, a1[13]); a2[13] = fmaf(xd.y, w2, a2[13]);
        a0[14] = fmaf(xd.z, w0, a0[14]); a1[14] = fmaf(xd.z, w1, a1[14]); a2[14] = fmaf(xd.z, w2, a2[14]);
        a0[15] = fmaf(xd.w, w0, a0[15]); a1[15] = fmaf(xd.w, w1, a1[15]); a2[15] = fmaf(xd.w, w2, a2[15]);
    }

    const float b0 = sB[tx];
    const float b1 = sB[tx + 32];
    const float b2 = sB[tx + 64];

#pragma unroll
    for (int i = 0; i < 16; i++) {
        int r = row0 + wr + i;
        if (r < n) {
            float m = g_mask[r] ? 1.f : 0.f;
            float* o = out + (size_t)r * DIM;
            o[tx]      = fmaxf(a0[i] + b0, 0.f) * m;
            o[tx + 32] = fmaxf(a1[i] + b1, 0.f) * m;
            o[tx + 64] = fmaxf(a2[i] + b2, 0.f) * m;
        }
    }
}

extern "C" void kernel_launch(void* const* d_in, const int* in_sizes, int n_in,
                              void* d_out, int out_size) {
    const float* x  = (const float*)d_in[0];
    // d_in[1] = p_t (unused, use_beta=False)
    const float* Wv = (const float*)d_in[2];
    const float* bv = (const float*)d_in[3];
    // d_in[4] = edge_weights (cancels: segment softmax sums to 1)
    const void*  ei = d_in[5];

    const int n = in_sizes[0] / DIM;                 // 50000
    const long long E = (long long)in_sizes[5] / 2;  // 800000

    {   // 1) fused detect + scatter (4 edges/thread)
        long long quads = (E + 3) / 4;
        int threads = 256;
        int blocks = (int)((quads + threads - 1) / threads);
        rd_scatter_kernel<<<blocks, threads>>>(ei, E, n);
    }
    {   // 2) masked GEMM + bias + relu
        int blocks = (n + RPB - 1) / RPB;            // 391
        rd_gemm_kernel<<<blocks, 256>>>(x, Wv, bv, (float*)d_out, n);
    }
}